// round 1
// baseline (speedup 1.0000x reference)
#include <cuda_runtime.h>

#define C_  512
#define Hh  24
#define Ww  24
#define HW  576
#define NH  8
#define HD  64
#define PW  30
#define PP  900
#define KP  960
#define SE_STRIDE 968

typedef unsigned long long ull;

// Scratch (device globals: allocation-free)
__device__ float g_Xp[C_ * KP];   // reflect-padded x, keys padded to 960 (zeros)
__device__ float g_Q [C_ * HW];   // Q[o][p]
__device__ float g_K [C_ * KP];   // K[o][pp]
__device__ float g_VT[KP * C_];   // V transposed: VT[pp][o]

// ---- packed fp32x2 helpers (sm_100+ double-rate FFMA2) ----
__device__ __forceinline__ void fma2(ull &d, ull a, ull b) {
    asm("fma.rn.f32x2 %0, %1, %2, %0;" : "+l"(d) : "l"(a), "l"(b));
}
__device__ __forceinline__ ull pk2(float x, float y) {
    ull r; asm("mov.b64 %0, {%1, %2};" : "=l"(r) : "f"(x), "f"(y)); return r;
}
__device__ __forceinline__ float2 upk(ull v) {
    float2 r; asm("mov.b64 {%0, %1}, %2;" : "=f"(r.x), "=f"(r.y) : "l"(v)); return r;
}

// ---------------------------------------------------------------------------
// Kernel 1: reflect-pad gather. g_Xp[c][pp] (pp = pr*30+pc), zeros for pp>=900.
// ---------------------------------------------------------------------------
__global__ void pad_kernel(const float* __restrict__ x) {
    int idx = blockIdx.x * 256 + threadIdx.x;
    if (idx >= C_ * KP) return;
    int c = idx / KP, pp = idx - c * KP;
    float v = 0.f;
    if (pp < PP) {
        int pr = pp / PW, pc = pp - pr * PW;
        int r = pr - 3; r = (r < 0) ? -r : ((r >= Hh) ? 2 * Hh - 2 - r : r);
        int cl = pc - 3; cl = (cl < 0) ? -cl : ((cl >= Ww) ? 2 * Ww - 2 - cl : cl);
        v = x[c * HW + r * Ww + cl];
    }
    g_Xp[idx] = v;
}

// ---------------------------------------------------------------------------
// Kernel 2: C[o][n] = W[o][c] * X[c][n] + b[o].  64x64 block tile, 256 thr,
// 4x4 per-thread micro-tile, fp32x2 packed FMA.
// mode 0: Q (X = x, N=576, normal)   mode 1: K (X=g_Xp, N=960, normal)
// mode 2: V (X = g_Xp, N=960, TRANSPOSED store into g_VT)
// ---------------------------------------------------------------------------
__global__ void gemm_kernel(const float* __restrict__ Wm, const float* __restrict__ bias,
                            const float* __restrict__ Xin, int mode) {
    __shared__ float sA[16 * 65];   // sA[cc_local][o_local]  (padded stride 65)
    __shared__ float sB[16 * 64];   // sB[cc_local][n_local]

    const float* X; float* Cout; int N; int transp = 0;
    if (mode == 0)      { X = Xin;  Cout = g_Q;  N = HW; }
    else if (mode == 1) { X = g_Xp; Cout = g_K;  N = KP; }
    else                { X = g_Xp; Cout = g_VT; N = KP; transp = 1; }

    int nB = blockIdx.x * 64, oB = blockIdx.y * 64;
    int tid = threadIdx.x;
    int tj = tid & 15, ti = tid >> 4;

    ull acc[4][2];
#pragma unroll
    for (int i = 0; i < 4; i++) { acc[i][0] = 0ULL; acc[i][1] = 0ULL; }

    int oo = tid >> 2, cg = (tid & 3) << 2;      // sA load: 64 rows x 4 float4 groups
    int tl = tid >> 4, n4 = (tid & 15) << 2;     // sB load: 16 rows x 16 float4 cols

    for (int cc = 0; cc < C_; cc += 16) {
        float4 w4 = *(const float4*)&Wm[(oB + oo) * C_ + cc + cg];
        float4 x4 = *(const float4*)&X[(cc + tl) * N + nB + n4];
        __syncthreads();
        sA[(cg + 0) * 65 + oo] = w4.x;
        sA[(cg + 1) * 65 + oo] = w4.y;
        sA[(cg + 2) * 65 + oo] = w4.z;
        sA[(cg + 3) * 65 + oo] = w4.w;
        *(float4*)&sB[tl * 64 + n4] = x4;
        __syncthreads();
#pragma unroll
        for (int t = 0; t < 16; t++) {
            float4 b = *(const float4*)&sB[t * 64 + (tj << 2)];
            ull b01 = pk2(b.x, b.y), b23 = pk2(b.z, b.w);
            const float* ar = &sA[t * 65 + (ti << 2)];
#pragma unroll
            for (int i = 0; i < 4; i++) {
                ull ab = pk2(ar[i], ar[i]);
                fma2(acc[i][0], ab, b01);
                fma2(acc[i][1], ab, b23);
            }
        }
    }
#pragma unroll
    for (int i = 0; i < 4; i++) {
        int o = oB + (ti << 2) + i;
        float bv = bias[o];
        float2 c01 = upk(acc[i][0]), c23 = upk(acc[i][1]);
        float4 cv = make_float4(c01.x + bv, c01.y + bv, c23.x + bv, c23.y + bv);
        if (!transp) {
            *(float4*)&Cout[o * N + nB + (tj << 2)] = cv;
        } else {
            int n = nB + (tj << 2);
            Cout[(n + 0) * C_ + o] = cv.x;
            Cout[(n + 1) * C_ + o] = cv.y;
            Cout[(n + 2) * C_ + o] = cv.z;
            Cout[(n + 3) * C_ + o] = cv.w;
        }
    }
}

// ---------------------------------------------------------------------------
// Kernel 3: fused attention over 960 (padded) deduplicated keys with
// multiplicity-weighted softmax. Grid (18 qtiles, 8 heads), 256 threads.
// Full E tile (32 x 960) lives in dynamic smem.
// ---------------------------------------------------------------------------
__global__ void attn_kernel(const float* __restrict__ x,
                            const float* __restrict__ gamma_p,
                            float* __restrict__ out) {
    extern __shared__ float sm[];
    float* sQ   = sm;                       // 64*32  = 2048 : sQ[d][q]
    float* sKV  = sm + 2048;                // 64*68  = 4352 : K chunk / V chunk
    float* sE   = sKV + 4352;               // 32*968 = 30976: E then P
    float* sInv = sE + 32 * SE_STRIDE;      // 32 : per-query 1/denominator

    int h   = blockIdx.y;
    int q0  = blockIdx.x * 32;
    int tid = threadIdx.x;
    int tx  = tid & 15, ty = tid >> 4;      // micro-tile coords

    // Load Q tile (d-major)
    for (int i = tid; i < 64 * 32; i += 256) {
        int d = i >> 5, q = i & 31;
        sQ[i] = g_Q[(h * HD + d) * HW + q0 + q];
    }
    __syncthreads();

    int dstg = tid >> 2;               // staging: row 0..63
    int cstg = (tid & 3) << 4;         // staging: col group 0/16/32/48

    // ---- Pass 1: E[q][k] = sum_d Q[d][q] * K[d][k] ----
    for (int kc = 0; kc < KP; kc += 64) {
        {   // stage K chunk: sKV[d][kloc], stride 64
            const float4* src = (const float4*)&g_K[(h * HD + dstg) * KP + kc + cstg];
            float4* dst = (float4*)&sKV[dstg * 64 + cstg];
            dst[0] = src[0]; dst[1] = src[1]; dst[2] = src[2]; dst[3] = src[3];
        }
        __syncthreads();
        ull e00 = 0, e01 = 0, e10 = 0, e11 = 0;
#pragma unroll
        for (int d = 0; d < 64; d++) {
            float2 a = *(const float2*)&sQ[d * 32 + (ty << 1)];
            float4 b = *(const float4*)&sKV[d * 64 + (tx << 2)];
            ull b01 = pk2(b.x, b.y), b23 = pk2(b.z, b.w);
            ull a0 = pk2(a.x, a.x), a1 = pk2(a.y, a.y);
            fma2(e00, a0, b01); fma2(e01, a0, b23);
            fma2(e10, a1, b01); fma2(e11, a1, b23);
        }
        {
            float2 p0 = upk(e00), p1 = upk(e01), p2 = upk(e10), p3 = upk(e11);
            int r0 = (ty << 1) * SE_STRIDE + kc + (tx << 2);
            *(float4*)&sE[r0]             = make_float4(p0.x, p0.y, p1.x, p1.y);
            *(float4*)&sE[r0 + SE_STRIDE] = make_float4(p2.x, p2.y, p3.x, p3.y);
        }
        __syncthreads();
    }

    // ---- Multiplicity-weighted softmax, in place: P = mult*exp(E-max) ----
    {
        int row = tid >> 3, part = tid & 7;      // 8 threads per query row
        float* Er = &sE[row * SE_STRIDE];
        int i0 = part * 120;
        float m = -1e30f;
        for (int i = i0; i < i0 + 120; i++) m = fmaxf(m, Er[i]);
        m = fmaxf(m, __shfl_xor_sync(~0u, m, 1));
        m = fmaxf(m, __shfl_xor_sync(~0u, m, 2));
        m = fmaxf(m, __shfl_xor_sync(~0u, m, 4));
        float s = 0.f;
        for (int i = i0; i < i0 + 120; i++) {
            float w = 0.f;
            if (i < PP) {
                int pr = i / PW, pc = i - pr * PW;
                int mr = min(pr + 1, min(7, PW - pr));
                int mc = min(pc + 1, min(7, PW - pc));
                w = (float)(mr * mc);
            }
            float p = w * __expf(Er[i] - m);
            Er[i] = p;
            s += p;
        }
        s += __shfl_xor_sync(~0u, s, 1);
        s += __shfl_xor_sync(~0u, s, 2);
        s += __shfl_xor_sync(~0u, s, 4);
        if (part == 0) sInv[row] = 1.f / s;
    }
    __syncthreads();

    // ---- Pass 2: out[q][d] = sum_k P[q][k] * VT[k][d] ----
    ull o00 = 0, o01 = 0, o10 = 0, o11 = 0;
    for (int kc = 0; kc < KP; kc += 64) {
        {   // stage V chunk: sKV[kloc][d], stride 68
            const float4* src = (const float4*)&g_VT[(kc + dstg) * C_ + h * HD + cstg];
            float4* dst = (float4*)&sKV[dstg * 68 + cstg];
            dst[0] = src[0]; dst[1] = src[1]; dst[2] = src[2]; dst[3] = src[3];
        }
        __syncthreads();
        int er0 = (ty << 1) * SE_STRIDE + kc;
#pragma unroll
        for (int k = 0; k < 64; k++) {
            float p0 = sE[er0 + k];
            float p1 = sE[er0 + SE_STRIDE + k];
            float4 v = *(const float4*)&sKV[k * 68 + (tx << 2)];
            ull v01 = pk2(v.x, v.y), v23 = pk2(v.z, v.w);
            ull pa = pk2(p0, p0), pb = pk2(p1, p1);
            fma2(o00, pa, v01); fma2(o01, pa, v23);
            fma2(o10, pb, v01); fma2(o11, pb, v23);
        }
        __syncthreads();
    }

    // ---- Epilogue: out = gamma * acc/denom + x ----
    float g = *gamma_p;
    float inv0 = sInv[(ty << 1)], inv1 = sInv[(ty << 1) + 1];
    float2 a0 = upk(o00), a1 = upk(o01), a2 = upk(o10), a3 = upk(o11);
    float v0[4] = {a0.x, a0.y, a1.x, a1.y};
    float v1[4] = {a2.x, a2.y, a3.x, a3.y};
    int qg = q0 + (ty << 1);
#pragma unroll
    for (int j = 0; j < 4; j++) {
        int o = h * HD + (tx << 2) + j;
        out[o * HW + qg]     = g * v0[j] * inv0 + x[o * HW + qg];
        out[o * HW + qg + 1] = g * v1[j] * inv1 + x[o * HW + qg + 1];
    }
}

// ---------------------------------------------------------------------------
extern "C" void kernel_launch(void* const* d_in, const int* in_sizes, int n_in,
                              void* d_out, int out_size) {
    const float* x     = (const float*)d_in[0];
    const float* Wq    = (const float*)d_in[1];
    const float* bq    = (const float*)d_in[2];
    const float* Wk    = (const float*)d_in[3];
    const float* bk    = (const float*)d_in[4];
    const float* Wv    = (const float*)d_in[5];
    const float* bv    = (const float*)d_in[6];
    const float* gamma = (const float*)d_in[7];
    float* out = (float*)d_out;

    pad_kernel<<<(C_ * KP + 255) / 256, 256>>>(x);
    gemm_kernel<<<dim3(HW / 64, C_ / 64), 256>>>(Wq, bq, x, 0);
    gemm_kernel<<<dim3(KP / 64, C_ / 64), 256>>>(Wk, bk, x, 1);
    gemm_kernel<<<dim3(KP / 64, C_ / 64), 256>>>(Wv, bv, x, 2);

    const int smem_bytes = (2048 + 4352 + 32 * SE_STRIDE + 32) * 4;  // 149632
    cudaFuncSetAttribute(attn_kernel, cudaFuncAttributeMaxDynamicSharedMemorySize, smem_bytes);
    attn_kernel<<<dim3(HW / 32, NH), 256, smem_bytes>>>(x, gamma, out);
}

// round 2
// speedup vs baseline: 1.1548x; 1.1548x over previous
#include <cuda_runtime.h>

#define C_  512
#define Hh  24
#define Ww  24
#define HW  576
#define NH  8
#define HD  64
#define PW  30
#define PP  900
#define KP  960
#define SE_STRIDE 968

typedef unsigned long long ull;

// Scratch (device globals: allocation-free)
__device__ float g_Xp[C_ * KP];   // reflect-padded x, keys padded to 960 (zeros)
__device__ float g_Q [C_ * HW];   // Q[o][p]
__device__ float g_K [C_ * KP];   // K[o][pp]
__device__ float g_VT[KP * C_];   // V transposed: VT[pp][o]

// ---- packed fp32x2 helpers ----
__device__ __forceinline__ void fma2(ull &d, ull a, ull b) {
    asm("fma.rn.f32x2 %0, %1, %2, %0;" : "+l"(d) : "l"(a), "l"(b));
}
__device__ __forceinline__ ull pk2(float x, float y) {
    ull r; asm("mov.b64 %0, {%1, %2};" : "=l"(r) : "f"(x), "f"(y)); return r;
}
__device__ __forceinline__ float2 upk(ull v) {
    float2 r; asm("mov.b64 {%0, %1}, %2;" : "=f"(r.x), "=f"(r.y) : "l"(v)); return r;
}

// ---------------------------------------------------------------------------
// Kernel 1: reflect-pad gather. g_Xp[c][pp] (pp = pr*30+pc), zeros for pp>=900.
// ---------------------------------------------------------------------------
__global__ void pad_kernel(const float* __restrict__ x) {
    int idx = blockIdx.x * 256 + threadIdx.x;
    if (idx >= C_ * KP) return;
    int c = idx / KP, pp = idx - c * KP;
    float v = 0.f;
    if (pp < PP) {
        int pr = pp / PW, pc = pp - pr * PW;
        int r = pr - 3; r = (r < 0) ? -r : ((r >= Hh) ? 2 * Hh - 2 - r : r);
        int cl = pc - 3; cl = (cl < 0) ? -cl : ((cl >= Ww) ? 2 * Ww - 2 - cl : cl);
        v = x[c * HW + r * Ww + cl];
    }
    g_Xp[idx] = v;
}

// ---------------------------------------------------------------------------
// Kernel 2 (fused): all three conv1x1 GEMMs in ONE launch, 312 CTAs.
//   bid [0,72)   : Q  = Wq @ x      (N=576)
//   bid [72,192) : K  = Wk @ Xp     (N=960)
//   bid [192,312): VT = (Wv @ Xp)^T (N=960, transposed store via smem)
// 64x64 tile, 256 threads, 4x4 micro-tile, fp32x2, double-buffered smem.
// ---------------------------------------------------------------------------
__global__ void __launch_bounds__(256) gemm_all_kernel(
    const float* __restrict__ Wq, const float* __restrict__ bq,
    const float* __restrict__ Wk, const float* __restrict__ bk,
    const float* __restrict__ Wv, const float* __restrict__ bv,
    const float* __restrict__ x)
{
    __shared__ float smem_g[4224];   // sA0[1088] sA1[1088] sB0[1024] sB1[1024]

    int bid = blockIdx.x;
    const float *Wm, *bias, *X; float* Cout; int N, transp = 0, nt, ot;
    if (bid < 72)       { nt = bid % 9;       ot = bid / 9;       Wm = Wq; bias = bq; X = x;    Cout = g_Q;  N = HW; }
    else if (bid < 192) { int b = bid - 72;   nt = b % 15; ot = b / 15; Wm = Wk; bias = bk; X = g_Xp; Cout = g_K;  N = KP; }
    else                { int b = bid - 192;  nt = b % 15; ot = b / 15; Wm = Wv; bias = bv; X = g_Xp; Cout = g_VT; N = KP; transp = 1; }
    int nB = nt * 64, oB = ot * 64;

    int tid = threadIdx.x;
    int tj = tid & 15, ti = tid >> 4;
    int oo = tid >> 2, cg = (tid & 3) << 2;      // sA stage: 64 o-rows x 4 float4 of c
    int tl = tid >> 4, n4 = (tid & 15) << 2;     // sB stage: 16 c-rows x 16 float4 of n

    float* sA[2] = { smem_g,        smem_g + 1088 };   // [c][o], stride 68
    float* sB[2] = { smem_g + 2176, smem_g + 3200 };   // [c][n], stride 64

    ull acc[4][2];
#pragma unroll
    for (int i = 0; i < 4; i++) { acc[i][0] = 0ULL; acc[i][1] = 0ULL; }

    // preload chunk 0
    {
        float4 w4 = *(const float4*)&Wm[(oB + oo) * C_ + cg];
        float4 x4 = *(const float4*)&X[tl * N + nB + n4];
        sA[0][(cg + 0) * 68 + oo] = w4.x;
        sA[0][(cg + 1) * 68 + oo] = w4.y;
        sA[0][(cg + 2) * 68 + oo] = w4.z;
        sA[0][(cg + 3) * 68 + oo] = w4.w;
        *(float4*)&sB[0][tl * 64 + n4] = x4;
    }
    __syncthreads();

    for (int cc = 0; cc < C_; cc += 16) {
        int cur = (cc >> 4) & 1;
        const float* cA = sA[cur];
        const float* cB = sB[cur];
        bool pf = cc + 16 < C_;
        float4 w4n, x4n;
        if (pf) {
            w4n = *(const float4*)&Wm[(oB + oo) * C_ + cc + 16 + cg];
            x4n = *(const float4*)&X[(cc + 16 + tl) * N + nB + n4];
        }
#pragma unroll
        for (int t = 0; t < 16; t++) {
            float4 b4 = *(const float4*)&cB[t * 64 + (tj << 2)];
            float4 a4 = *(const float4*)&cA[t * 68 + (ti << 2)];
            ull b01 = pk2(b4.x, b4.y), b23 = pk2(b4.z, b4.w);
            ull a0 = pk2(a4.x, a4.x), a1 = pk2(a4.y, a4.y);
            ull a2 = pk2(a4.z, a4.z), a3 = pk2(a4.w, a4.w);
            fma2(acc[0][0], a0, b01); fma2(acc[0][1], a0, b23);
            fma2(acc[1][0], a1, b01); fma2(acc[1][1], a1, b23);
            fma2(acc[2][0], a2, b01); fma2(acc[2][1], a2, b23);
            fma2(acc[3][0], a3, b01); fma2(acc[3][1], a3, b23);
        }
        if (pf) {
            float* nA = sA[cur ^ 1];
            float* nBp = sB[cur ^ 1];
            nA[(cg + 0) * 68 + oo] = w4n.x;
            nA[(cg + 1) * 68 + oo] = w4n.y;
            nA[(cg + 2) * 68 + oo] = w4n.z;
            nA[(cg + 3) * 68 + oo] = w4n.w;
            *(float4*)&nBp[tl * 64 + n4] = x4n;
        }
        __syncthreads();
    }

    // epilogue
    float4 cv[4];
#pragma unroll
    for (int i = 0; i < 4; i++) {
        float bv_ = bias[oB + (ti << 2) + i];
        float2 c01 = upk(acc[i][0]), c23 = upk(acc[i][1]);
        cv[i] = make_float4(c01.x + bv_, c01.y + bv_, c23.x + bv_, c23.y + bv_);
    }
    if (!transp) {
#pragma unroll
        for (int i = 0; i < 4; i++)
            *(float4*)&Cout[(oB + (ti << 2) + i) * N + nB + (tj << 2)] = cv[i];
    } else {
        // transpose through smem for coalesced VT stores
        // (all compute done: loop ended with __syncthreads)
#pragma unroll
        for (int i = 0; i < 4; i++) {
            smem_g[((tj << 2) + 0) * 65 + (ti << 2) + i] = cv[i].x;
            smem_g[((tj << 2) + 1) * 65 + (ti << 2) + i] = cv[i].y;
            smem_g[((tj << 2) + 2) * 65 + (ti << 2) + i] = cv[i].z;
            smem_g[((tj << 2) + 3) * 65 + (ti << 2) + i] = cv[i].w;
        }
        __syncthreads();
#pragma unroll
        for (int it = 0; it < 16; it++) {
            int idx = it * 256 + tid;
            int n = idx >> 6, o = idx & 63;
            Cout[(nB + n) * C_ + oB + o] = smem_g[n * 65 + o];
        }
    }
}

// ---------------------------------------------------------------------------
// Kernel 3: fused attention over 960 (padded) deduplicated keys with
// multiplicity-weighted softmax. Grid (18 qtiles, 8 heads) = 144 CTAs.
// Double-buffered K/V staging; full 32x960 E tile in smem.
// ---------------------------------------------------------------------------
__global__ void __launch_bounds__(256) attn_kernel(const float* __restrict__ x,
                            const float* __restrict__ gamma_p,
                            float* __restrict__ out) {
    extern __shared__ float sm[];
    float* sQ   = sm;                      // 64*32  = 2048 : sQ[d][q]
    float* sKV0 = sm + 2048;               // 64*68  = 4352
    float* sKV1 = sKV0 + 4352;             // 64*68  = 4352
    float* sE   = sKV1 + 4352;             // 32*968 = 30976
    float* sInv = sE + 32 * SE_STRIDE;     // 32

    int h   = blockIdx.y;
    int q0  = blockIdx.x * 32;
    int tid = threadIdx.x;
    int tx  = tid & 15, ty = tid >> 4;
    int tx4 = tx << 2;
    int dstg = tid >> 2, cstg = (tid & 3) << 4;
    float* sKVb[2] = { sKV0, sKV1 };

    // Load Q tile (d-major), vectorized
    for (int i = tid; i < 64 * 8; i += 256) {
        int d = i >> 3, qg = (i & 7) << 2;
        *(float4*)&sQ[d * 32 + qg] = *(const float4*)&g_Q[(h * HD + d) * HW + q0 + qg];
    }
    // preload K chunk 0
    {
        const float4* src = (const float4*)&g_K[(h * HD + dstg) * KP + cstg];
        float4 r0 = src[0], r1 = src[1], r2 = src[2], r3 = src[3];
        float4* dst = (float4*)&sKV0[dstg * 68 + cstg];
        dst[0] = r0; dst[1] = r1; dst[2] = r2; dst[3] = r3;
    }
    __syncthreads();

    // ---- Pass 1: E[q][k] = sum_d Q[d][q] * K[d][k] ----
    for (int kc = 0; kc < KP; kc += 64) {
        int cur = (kc >> 6) & 1;
        const float* cKV = sKVb[cur];
        bool pf = kc + 64 < KP;
        float4 r0, r1, r2, r3;
        if (pf) {
            const float4* src = (const float4*)&g_K[(h * HD + dstg) * KP + kc + 64 + cstg];
            r0 = src[0]; r1 = src[1]; r2 = src[2]; r3 = src[3];
        }
        ull e00 = 0, e01 = 0, e10 = 0, e11 = 0;
#pragma unroll 16
        for (int d = 0; d < 64; d++) {
            float2 a = *(const float2*)&sQ[d * 32 + (ty << 1)];
            float4 b = *(const float4*)&cKV[d * 68 + tx4];
            ull b01 = pk2(b.x, b.y), b23 = pk2(b.z, b.w);
            ull a0 = pk2(a.x, a.x), a1 = pk2(a.y, a.y);
            fma2(e00, a0, b01); fma2(e01, a0, b23);
            fma2(e10, a1, b01); fma2(e11, a1, b23);
        }
        {
            float2 p0 = upk(e00), p1 = upk(e01), p2 = upk(e10), p3 = upk(e11);
            int r = (ty << 1) * SE_STRIDE + kc + tx4;
            *(float4*)&sE[r]             = make_float4(p0.x, p0.y, p1.x, p1.y);
            *(float4*)&sE[r + SE_STRIDE] = make_float4(p2.x, p2.y, p3.x, p3.y);
        }
        if (pf) {
            float4* dst = (float4*)&sKVb[cur ^ 1][dstg * 68 + cstg];
            dst[0] = r0; dst[1] = r1; dst[2] = r2; dst[3] = r3;
        }
        __syncthreads();
    }

    // issue V chunk-0 global loads early; they complete under softmax
    float4 v0r, v1r, v2r, v3r;
    {
        const float4* src = (const float4*)&g_VT[dstg * C_ + h * HD + cstg];
        v0r = src[0]; v1r = src[1]; v2r = src[2]; v3r = src[3];
    }

    // ---- Multiplicity-weighted softmax, in place: P = mult*exp(E-max) ----
    {
        int row = tid >> 3, part = tid & 7;      // 8 threads per query row
        float* Er = &sE[row * SE_STRIDE];
        int i0 = part * 120;
        float m = -1e30f;
        for (int i = i0; i < i0 + 120; i++) m = fmaxf(m, Er[i]);
        m = fmaxf(m, __shfl_xor_sync(~0u, m, 1));
        m = fmaxf(m, __shfl_xor_sync(~0u, m, 2));
        m = fmaxf(m, __shfl_xor_sync(~0u, m, 4));
        float s = 0.f;
        for (int i = i0; i < i0 + 120; i++) {
            float w = 0.f;
            if (i < PP) {
                int pr = i / PW, pc = i - pr * PW;
                int mr = min(pr + 1, min(7, PW - pr));
                int mc = min(pc + 1, min(7, PW - pc));
                w = (float)(mr * mc);
            }
            float p = w * __expf(Er[i] - m);
            Er[i] = p;
            s += p;
        }
        s += __shfl_xor_sync(~0u, s, 1);
        s += __shfl_xor_sync(~0u, s, 2);
        s += __shfl_xor_sync(~0u, s, 4);
        if (part == 0) sInv[row] = 1.f / s;
    }
    // store V chunk 0 (pass 1 / softmax no longer touch sKV0)
    {
        float4* dst = (float4*)&sKV0[dstg * 68 + cstg];
        dst[0] = v0r; dst[1] = v1r; dst[2] = v2r; dst[3] = v3r;
    }
    __syncthreads();

    // ---- Pass 2: out[q][d] = sum_k P[q][k] * VT[k][d] ----
    ull o00 = 0, o01 = 0, o10 = 0, o11 = 0;
    for (int kc = 0; kc < KP; kc += 64) {
        int cur = (kc >> 6) & 1;
        const float* cKV = sKVb[cur];
        bool pf = kc + 64 < KP;
        float4 r0, r1, r2, r3;
        if (pf) {
            const float4* src = (const float4*)&g_VT[(kc + 64 + dstg) * C_ + h * HD + cstg];
            r0 = src[0]; r1 = src[1]; r2 = src[2]; r3 = src[3];
        }
        const float* sEr0 = &sE[(ty << 1) * SE_STRIDE + kc];
        const float* sEr1 = sEr0 + SE_STRIDE;
#pragma unroll 8
        for (int k = 0; k < 64; k += 2) {
            float2 pa = *(const float2*)&sEr0[k];
            float2 pb = *(const float2*)&sEr1[k];
            float4 va = *(const float4*)&cKV[k * 68 + tx4];
            float4 vb = *(const float4*)&cKV[(k + 1) * 68 + tx4];
            ull va01 = pk2(va.x, va.y), va23 = pk2(va.z, va.w);
            ull vb01 = pk2(vb.x, vb.y), vb23 = pk2(vb.z, vb.w);
            ull pax = pk2(pa.x, pa.x), pbx = pk2(pb.x, pb.x);
            ull pay = pk2(pa.y, pa.y), pby = pk2(pb.y, pb.y);
            fma2(o00, pax, va01); fma2(o01, pax, va23);
            fma2(o10, pbx, va01); fma2(o11, pbx, va23);
            fma2(o00, pay, vb01); fma2(o01, pay, vb23);
            fma2(o10, pby, vb01); fma2(o11, pby, vb23);
        }
        if (pf) {
            float4* dst = (float4*)&sKVb[cur ^ 1][dstg * 68 + cstg];
            dst[0] = r0; dst[1] = r1; dst[2] = r2; dst[3] = r3;
        }
        __syncthreads();
    }

    // ---- Epilogue via smem transpose: out = gamma*acc/denom + x, coalesced ----
    {
        float2 a0 = upk(o00), a1 = upk(o01), a2 = upk(o10), a3 = upk(o11);
        float v0[4] = {a0.x, a0.y, a1.x, a1.y};
        float v1[4] = {a2.x, a2.y, a3.x, a3.y};
        float* sOut = sKV0;                       // 64 x 33 <= 4352, loop-end sync passed
        int qr = ty << 1;
#pragma unroll
        for (int j = 0; j < 4; j++) {
            sOut[(tx4 + j) * 33 + qr]     = v0[j];
            sOut[(tx4 + j) * 33 + qr + 1] = v1[j];
        }
        __syncthreads();
        float g = *gamma_p;
        for (int i = tid; i < 64 * 32; i += 256) {
            int d = i >> 5, q = i & 31;
            int gi = (h * HD + d) * HW + q0 + q;
            out[gi] = g * sOut[d * 33 + q] * sInv[q] + x[gi];
        }
    }
}

// ---------------------------------------------------------------------------
extern "C" void kernel_launch(void* const* d_in, const int* in_sizes, int n_in,
                              void* d_out, int out_size) {
    const float* x     = (const float*)d_in[0];
    const float* Wq    = (const float*)d_in[1];
    const float* bq    = (const float*)d_in[2];
    const float* Wk    = (const float*)d_in[3];
    const float* bk    = (const float*)d_in[4];
    const float* Wv    = (const float*)d_in[5];
    const float* bv    = (const float*)d_in[6];
    const float* gamma = (const float*)d_in[7];
    float* out = (float*)d_out;

    pad_kernel<<<(C_ * KP + 255) / 256, 256>>>(x);
    gemm_all_kernel<<<312, 256>>>(Wq, bq, Wk, bk, Wv, bv, x);

    const int smem_bytes = (2048 + 2 * 4352 + 32 * SE_STRIDE + 32) * 4;  // 167040
    cudaFuncSetAttribute(attn_kernel, cudaFuncAttributeMaxDynamicSharedMemorySize, smem_bytes);
    attn_kernel<<<dim3(HW / 32, NH), 256, smem_bytes>>>(x, gamma, out);
}